// round 14
// baseline (speedup 1.0000x reference)
#include <cuda_runtime.h>
#include <cuda_bf16.h>
#include <cstdint>
#include <cstddef>

// Problem dims
#define B_ 256
#define T_ 512
#define D_ 512
#define H_ 1024
#define O_ 512

constexpr int    BH  = B_ * H_;                      // 262144
constexpr size_t BTH = (size_t)B_ * T_ * H_;         // 134217728
constexpr size_t BTO = (size_t)B_ * T_ * O_;         // 67108864
constexpr size_t BTD = (size_t)B_ * T_ * D_;         // 67108864

// ---------------- scratch (static __device__ arrays; no runtime alloc) ----
__device__ __align__(16) float         g_P[BTH];                     // [t][b][h]
__device__ __align__(16) __nv_bfloat16 g_Hhi[(size_t)(T_ + 1) * BH]; // split h, hi
__device__ __align__(16) __nv_bfloat16 g_Hlo[(size_t)(T_ + 1) * BH]; // split h, lo
__device__ __align__(16) __nv_bfloat16 g_Xhi[BTD], g_Xlo[BTD];       // split x
__device__ __align__(16) __nv_bfloat16 g_Wxh_hi[D_ * H_], g_Wxh_lo[D_ * H_];
__device__ __align__(16) __nv_bfloat16 g_Whh_hi[H_ * H_], g_Whh_lo[H_ * H_];
__device__ __align__(16) __nv_bfloat16 g_Why_hi[H_ * O_], g_Why_lo[H_ * O_];
__device__ unsigned      g_bar[4 * 32];              // group barriers (128B apart)

// ---------------- PTX helpers ---------------------------------------------
__device__ __forceinline__ void mma_bf16(float* c, const uint32_t* a, const uint32_t* b) {
    asm volatile(
        "mma.sync.aligned.m16n8k16.row.col.f32.bf16.bf16.f32 "
        "{%0,%1,%2,%3}, {%4,%5,%6,%7}, {%8,%9}, {%0,%1,%2,%3};\n"
        : "+f"(c[0]), "+f"(c[1]), "+f"(c[2]), "+f"(c[3])
        : "r"(a[0]), "r"(a[1]), "r"(a[2]), "r"(a[3]), "r"(b[0]), "r"(b[1]));
}
__device__ __forceinline__ void ldsm_x4(uint32_t* r, uint32_t saddr) {
    asm volatile("ldmatrix.sync.aligned.m8n8.x4.shared.b16 {%0,%1,%2,%3}, [%4];"
                 : "=r"(r[0]), "=r"(r[1]), "=r"(r[2]), "=r"(r[3]) : "r"(saddr));
}
__device__ __forceinline__ void ldsm_x4_t(uint32_t* r, uint32_t saddr) {
    asm volatile("ldmatrix.sync.aligned.m8n8.x4.trans.shared.b16 {%0,%1,%2,%3}, [%4];"
                 : "=r"(r[0]), "=r"(r[1]), "=r"(r[2]), "=r"(r[3]) : "r"(saddr));
}
__device__ __forceinline__ void cpasync16(uint32_t smem_addr, const void* gmem) {
    asm volatile("cp.async.ca.shared.global [%0], [%1], 16;\n"
                 :: "r"(smem_addr), "l"(gmem));
}
__device__ __forceinline__ void cp_commit() {
    asm volatile("cp.async.commit_group;\n" ::: "memory");
}
template <int N>
__device__ __forceinline__ void cp_wait() {
    asm volatile("cp.async.wait_group %0;\n" :: "n"(N) : "memory");
}
__device__ __forceinline__ void red_release_add(unsigned* p) {
    asm volatile("red.release.gpu.global.add.u32 [%0], 1;" :: "l"(p) : "memory");
}
__device__ __forceinline__ unsigned ld_acquire(const unsigned* p) {
    unsigned v;
    asm volatile("ld.acquire.gpu.u32 %0, [%1];" : "=r"(v) : "l"(p));
    return v;
}
__device__ __forceinline__ uint32_t pack_bf162(__nv_bfloat16 a, __nv_bfloat16 b) {
    __nv_bfloat162 t; t.x = a; t.y = b;
    uint32_t r;
    __builtin_memcpy(&r, &t, 4);
    return r;
}

// =================== big GEMM (P and Y) geometry ===========================
constexpr int SGA   = 40;
constexpr int SBN   = 136;
constexpr int GA_PL = 128 * SGA * 2;           // 10240 B per A plane
constexpr int GB_PL = 32 * SBN * 2;            // 8704 B per B plane
constexpr int G_STAGE = 2 * GA_PL + 2 * GB_PL; // 37888
constexpr int SMEM_G  = 2 * G_STAGE;           // 75776

__device__ __forceinline__ void g_loadB(uint32_t st, const __nv_bfloat16* Bhi,
                                        const __nv_bfloat16* Blo, int ldb,
                                        int n0, int k0, int tid)
{
#pragma unroll
    for (int j = 0; j < 4; j++) {
        int idx = j * 256 + tid;
        int plane = idx >> 9, rem = idx & 511;
        int k = rem >> 4, n16 = rem & 15;
        const __nv_bfloat16* src = (plane ? Blo : Bhi) + (size_t)(k0 + k) * ldb + n0 + n16 * 8;
        cpasync16(st + 2 * GA_PL + plane * GB_PL + (uint32_t)(k * SBN + n16 * 8) * 2, src);
    }
}

__device__ __forceinline__ void g_compute(uint32_t stA, uint32_t aoff, uint32_t boff,
                                          float acc[2][8][4])
{
    uint32_t stB = stA + 2 * GA_PL;
#pragma unroll
    for (int ks = 0; ks < 32; ks += 16) {
        uint32_t ah0[4], ah1[4], al0[4], al1[4];
        ldsm_x4(ah0, stA + aoff + ks * 2);
        ldsm_x4(ah1, stA + aoff + ks * 2 + 16 * SGA * 2);
        ldsm_x4(al0, stA + GA_PL + aoff + ks * 2);
        ldsm_x4(al1, stA + GA_PL + aoff + ks * 2 + 16 * SGA * 2);
#pragma unroll
        for (int hn = 0; hn < 2; hn++) {
            uint32_t bb0 = stB + boff + (uint32_t)(ks * SBN + hn * 32) * 2;
            uint32_t bh0[4], bh1[4], bl0[4], bl1[4];
            ldsm_x4_t(bh0, bb0);
            ldsm_x4_t(bh1, bb0 + 32);
            ldsm_x4_t(bl0, bb0 + GB_PL);
            ldsm_x4_t(bl1, bb0 + GB_PL + 32);
#pragma unroll
            for (int mf = 0; mf < 2; mf++) {
                const uint32_t* Ah = mf ? ah1 : ah0;
                const uint32_t* Al = mf ? al1 : al0;
                float* a0 = acc[mf][hn * 4 + 0];
                float* a1 = acc[mf][hn * 4 + 1];
                float* a2 = acc[mf][hn * 4 + 2];
                float* a3 = acc[mf][hn * 4 + 3];
                mma_bf16(a0, Ah, bh0 + 0);  mma_bf16(a1, Ah, bh0 + 2);
                mma_bf16(a2, Ah, bh1 + 0);  mma_bf16(a3, Ah, bh1 + 2);
                mma_bf16(a0, Ah, bl0 + 0);  mma_bf16(a1, Ah, bl0 + 2);
                mma_bf16(a2, Ah, bl1 + 0);  mma_bf16(a3, Ah, bl1 + 2);
                mma_bf16(a0, Al, bh0 + 0);  mma_bf16(a1, Al, bh0 + 2);
                mma_bf16(a2, Al, bh1 + 0);  mma_bf16(a3, Al, bh1 + 2);
            }
        }
    }
}

// ---------------- kernel: P = split(X) @ split(W_xh), out [t][b][h] -------
__global__ __launch_bounds__(256, 2) void gemm_P_kernel()
{
    extern __shared__ __align__(16) char gsm[];
    uint32_t sb = (uint32_t)__cvta_generic_to_shared(gsm);
    int tid = threadIdx.x, lane = tid & 31, warp = tid >> 5;
    int g = lane >> 2, tg = lane & 3;
    int wm = (warp >> 1) * 32, wn = (warp & 1) * 64;
    int n0 = blockIdx.x * 128;
    int m0 = blockIdx.y * 128;
    const int NK = D_ / 32;  // 16

    const uint32_t aoff =
        (uint32_t)((wm + ((lane >> 3) & 1) * 8 + (lane & 7)) * SGA + (lane >> 4) * 8) * 2;
    const uint32_t boff =
        (uint32_t)((((lane >> 3) & 1) * 8 + (lane & 7)) * SBN + wn + (lane >> 4) * 8) * 2;

    float acc[2][8][4];
#pragma unroll
    for (int a = 0; a < 2; a++)
#pragma unroll
        for (int b = 0; b < 8; b++)
#pragma unroll
            for (int c = 0; c < 4; c++) acc[a][b][c] = 0.f;

#pragma unroll
    for (int j = 0; j < 4; j++) {
        int idx = j * 256 + tid;
        int plane = idx >> 9, rem = idx & 511;
        int r = rem >> 2, c4 = rem & 3;
        const __nv_bfloat16* src = (plane ? g_Xlo : g_Xhi) + (size_t)(m0 + r) * D_ + c4 * 8;
        cpasync16(sb + plane * GA_PL + (uint32_t)(r * SGA + c4 * 8) * 2, src);
    }
    g_loadB(sb, g_Wxh_hi, g_Wxh_lo, H_, n0, 0, tid);
    cp_commit();

    for (int kt = 0; kt < NK; kt++) {
        if (kt + 1 < NK) {
            uint32_t st = sb + ((kt + 1) & 1) * G_STAGE;
            int k0 = (kt + 1) * 32;
#pragma unroll
            for (int j = 0; j < 4; j++) {
                int idx = j * 256 + tid;
                int plane = idx >> 9, rem = idx & 511;
                int r = rem >> 2, c4 = rem & 3;
                const __nv_bfloat16* src =
                    (plane ? g_Xlo : g_Xhi) + (size_t)(m0 + r) * D_ + k0 + c4 * 8;
                cpasync16(st + plane * GA_PL + (uint32_t)(r * SGA + c4 * 8) * 2, src);
            }
            g_loadB(st, g_Wxh_hi, g_Wxh_lo, H_, n0, k0, tid);
            cp_commit();
            cp_wait<1>();
        } else {
            cp_wait<0>();
        }
        __syncthreads();
        g_compute(sb + (kt & 1) * G_STAGE, aoff, boff, acc);
        __syncthreads();
    }

#pragma unroll
    for (int mf = 0; mf < 2; mf++)
#pragma unroll
        for (int nf = 0; nf < 8; nf++) {
            int c = n0 + wn + nf * 8 + tg * 2;
#pragma unroll
            for (int half = 0; half < 2; half++) {
                int r = m0 + wm + mf * 16 + g + half * 8;
                int tt = r & (T_ - 1);
                int bb = r >> 9;
                float2 v;
                v.x = acc[mf][nf][half * 2];
                v.y = acc[mf][nf][half * 2 + 1];
                *(float2*)(g_P + ((size_t)tt * B_ + bb) * H_ + c) = v;
            }
        }
}

// ---------------- kernel: Y = H_all @ W_hy --------------------------------
__global__ __launch_bounds__(256, 2) void gemm_Y_kernel(float* __restrict__ out)
{
    extern __shared__ __align__(16) char gsm[];
    uint32_t sb = (uint32_t)__cvta_generic_to_shared(gsm);
    int tid = threadIdx.x, lane = tid & 31, warp = tid >> 5;
    int g = lane >> 2, tg = lane & 3;
    int wm = (warp >> 1) * 32, wn = (warp & 1) * 64;
    int n0 = blockIdx.x * 128;
    int m0 = blockIdx.y * 128;
    const int NK = H_ / 32;  // 32

    const uint32_t aoff =
        (uint32_t)((wm + ((lane >> 3) & 1) * 8 + (lane & 7)) * SGA + (lane >> 4) * 8) * 2;
    const uint32_t boff =
        (uint32_t)((((lane >> 3) & 1) * 8 + (lane & 7)) * SBN + wn + (lane >> 4) * 8) * 2;

    float acc[2][8][4];
#pragma unroll
    for (int a = 0; a < 2; a++)
#pragma unroll
        for (int b = 0; b < 8; b++)
#pragma unroll
            for (int c = 0; c < 4; c++) acc[a][b][c] = 0.f;

#pragma unroll
    for (int j = 0; j < 4; j++) {
        int idx = j * 256 + tid;
        int plane = idx >> 9, rem = idx & 511;
        int r = rem >> 2, c4 = rem & 3;
        int m = m0 + r;
        int tt = m & (T_ - 1), bb = m >> 9;
        const __nv_bfloat16* src = (plane ? g_Hlo : g_Hhi) +
            (size_t)(tt + 1) * BH + (size_t)bb * H_ + c4 * 8;
        cpasync16(sb + plane * GA_PL + (uint32_t)(r * SGA + c4 * 8) * 2, src);
    }
    g_loadB(sb, g_Why_hi, g_Why_lo, O_, n0, 0, tid);
    cp_commit();

    for (int kt = 0; kt < NK; kt++) {
        if (kt + 1 < NK) {
            uint32_t st = sb + ((kt + 1) & 1) * G_STAGE;
            int k0 = (kt + 1) * 32;
#pragma unroll
            for (int j = 0; j < 4; j++) {
                int idx = j * 256 + tid;
                int plane = idx >> 9, rem = idx & 511;
                int r = rem >> 2, c4 = rem & 3;
                int m = m0 + r;
                int tt = m & (T_ - 1), bb = m >> 9;
                const __nv_bfloat16* src = (plane ? g_Hlo : g_Hhi) +
                    (size_t)(tt + 1) * BH + (size_t)bb * H_ + k0 + c4 * 8;
                cpasync16(st + plane * GA_PL + (uint32_t)(r * SGA + c4 * 8) * 2, src);
            }
            g_loadB(st, g_Why_hi, g_Why_lo, O_, n0, k0, tid);
            cp_commit();
            cp_wait<1>();
        } else {
            cp_wait<0>();
        }
        __syncthreads();
        g_compute(sb + (kt & 1) * G_STAGE, aoff, boff, acc);
        __syncthreads();
    }

#pragma unroll
    for (int mf = 0; mf < 2; mf++)
#pragma unroll
        for (int nf = 0; nf < 8; nf++) {
            int c = n0 + wn + nf * 8 + tg * 2;
#pragma unroll
            for (int half = 0; half < 2; half++) {
                size_t r = (size_t)m0 + wm + mf * 16 + g + half * 8;
                float2 v;
                v.x = acc[mf][nf][half * 2];
                v.y = acc[mf][nf][half * 2 + 1];
                *(float2*)(out + r * O_ + c) = v;
            }
        }
}

// =================== persistent recurrence kernel ==========================
// 128 CTAs = 4 groups (64 batch rows) x 32 n-tiles (32 cols), 256 thr (8 warps).
// Register-resident W_hh-hi (k-interleaved), W_hh-lo in smem, per-warp 64x32
// k-partials reduced through smem, full group barrier (proven R11 core).
// NEW (R13): each warp cp.async-loads ONLY its own k16 slice of each A chunk
// into a private 3-stage ring (48B rows, conflict-free ldsm) -> zero
// __syncthreads in the chunk loop; warps fully decoupled within a step.
constexpr int SW       = 1032;                       // W-lo slab row stride (elems)
constexpr int SM_WLO   = 1024;
constexpr int SM_AW    = SM_WLO + 32 * SW * 2;       // 67072
constexpr int AW_ROW   = 48;                         // bytes per A row (32B data)
constexpr int AW_PLANE = 64 * AW_ROW;                // 3072 B
constexpr int AW_STAGE = 2 * AW_PLANE;               // 6144 B (hi+lo)
constexpr int AW_WARP  = 3 * AW_STAGE;               // 18432 B per warp
constexpr int SMEM_RNN = SM_AW + 8 * AW_WARP;        // 214528 B
constexpr int PART_STR = 36;                         // partial stride (floats)

__global__ __launch_bounds__(256, 1) void rnn_persistent_kernel()
{
    extern __shared__ __align__(1024) char smem[];
    uint32_t sb = (uint32_t)__cvta_generic_to_shared(smem);

    const int tid  = threadIdx.x;
    const int lane = tid & 31, warp = tid >> 5;      // 8 warps
    const int g = lane >> 2, tg = lane & 3;
    const int grp = (int)(blockIdx.x >> 5);
    const int m0 = grp * 64;
    const int n0 = (int)(blockIdx.x & 31) * 32;
    const int off = (int)(blockIdx.x & 7);           // chunk stagger (8 chunks)
    unsigned* bar = &g_bar[grp * 32];

    // ---- load W-lo slab (resident) + W-hi temp slab (ring area) ----
    __nv_bfloat16* sWlo  = (__nv_bfloat16*)(smem + SM_WLO);
    __nv_bfloat16* sWhiT = (__nv_bfloat16*)(smem + SM_AW);
    for (int idx = tid; idx < 32 * 1024; idx += 256) {
        int n = idx & 31, k = idx >> 5;
        sWlo[n * SW + k]  = g_Whh_lo[(size_t)k * H_ + n0 + n];
        sWhiT[n * SW + k] = g_Whh_hi[(size_t)k * H_ + n0 + n];
    }
    __syncthreads();

    // ---- B lane addressing ----
    const int bn  = (lane >> 4) * 8 + (lane & 7);    // n within 16-group
    const int kb  = ((lane >> 3) & 1) * 8;           // k8 offset
    // W-hi fragments -> registers; Bh[i] holds the i-th PROCESSED chunk
    uint32_t Bh[8][8];
#pragma unroll
    for (int i = 0; i < 8; i++) {
        int cl = (i + off) & 7;
        int k16 = cl * 8 + warp;                     // global k16 index
        uint32_t a0 = sb + SM_AW + (uint32_t)(bn * SW + k16 * 16 + kb) * 2;
        uint32_t a1 = a0 + (uint32_t)(16 * SW) * 2;
        ldsm_x4(&Bh[i][0], a0);
        ldsm_x4(&Bh[i][4], a1);
    }
    __syncthreads();    // W-hi temp slab now free (ring area)

    // ---- per-warp A ring addressing ----
    const uint32_t wbase = sb + SM_AW + (uint32_t)warp * AW_WARP;
    const int a_row = (lane & 7) + ((lane >> 3) & 1) * 8;    // 0..15
    const uint32_t a_u16 = (uint32_t)((lane >> 4) * 16);     // 16B unit
    uint32_t aoffs[4];
#pragma unroll
    for (int mf = 0; mf < 4; mf++)
        aoffs[mf] = (uint32_t)((mf * 16 + a_row) * AW_ROW) + a_u16;
    const uint32_t blo0 = sb + SM_WLO + (uint32_t)(bn * SW + warp * 16 + kb) * 2;
    const uint32_t blo1 = blo0 + (uint32_t)(16 * SW) * 2;

    // ---- epilogue mapping ----
    const int em  = tid >> 2;                        // 0..63 output row
    const int enq = tid & 3;                         // n-quad (8 cols)

    float* part = (float*)(smem + SM_AW);            // overlays ring area

    // P prefetch for t = 0
    float2 pre[2][2];
    {
        const float* Pt = g_P;
        // rows for this thread's MMA outputs: a_row-pattern rows, but the
        // epilogue uses (em, enq) mapping after the smem reduce, so prefetch
        // uses (em, enq) too.
        const float* Pp = Pt + (size_t)(m0 + em) * H_ + n0 + enq * 8;
        pre[0][0] = *(const float2*)(Pp);
        pre[0][1] = *(const float2*)(Pp + 2);
        pre[1][0] = *(const float2*)(Pp + 4);
        pre[1][1] = *(const float2*)(Pp + 6);
    }

    for (int t = 0; t < T_; t++) {
        const __nv_bfloat16* bHi = g_Hhi + (size_t)t * BH + (size_t)m0 * H_;
        const __nv_bfloat16* bLo = g_Hlo + (size_t)t * BH + (size_t)m0 * H_;

        float acc[4][4][4];
#pragma unroll
        for (int a = 0; a < 4; a++)
#pragma unroll
            for (int b = 0; b < 4; b++)
#pragma unroll
                for (int e = 0; e < 4; e++) acc[a][b][e] = 0.f;

        // ---- per-warp prologue: chunks (off), (off+1) into stages 0, 1 ----
        // per warp per chunk: 64 rows x 32B (its k16) x 2 planes = 256 x 16B
#pragma unroll
        for (int pk = 0; pk < 2; pk++) {
            int cl = (pk + off) & 7;
            uint32_t stb = wbase + pk * AW_STAGE;
#pragma unroll
            for (int j = 0; j < 8; j++) {
                int idx = j * 32 + lane;
                int plane = idx >> 7, rem = idx & 127;
                int row = rem >> 1, u = rem & 1;
                uint32_t dst = stb + plane * AW_PLANE +
                               (uint32_t)(row * AW_ROW + u * 16);
                const __nv_bfloat16* src =
                    (plane ? bLo : bHi) + (size_t)row * H_ + cl * 128 + warp * 16 + u * 8;
                cpasync16(dst, src);
            }
            cp_commit();
        }

        // ---- chunk loop: NO __syncthreads; warp-private pipeline ----
        for (int kt = 0; kt < 8; kt++) {
            if (kt + 2 < 8) {
                int s2 = (kt + 2) % 3;
                int cl2 = (kt + 2 + off) & 7;
                uint32_t stb = wbase + s2 * AW_STAGE;
#pragma unroll
                for (int j = 0; j < 8; j++) {
                    int idx = j * 32 + lane;
                    int plane = idx >> 7, rem = idx & 127;
                    int row = rem >> 1, u = rem & 1;
                    uint32_t dst = stb + plane * AW_PLANE +
                                   (uint32_t)(row * AW_ROW + u * 16);
                    const __nv_bfloat16* src =
                        (plane ? bLo : bHi) + (size_t)row * H_ + cl2 * 128 + warp * 16 + u * 8;
                    cpasync16(dst, src);
                }
                cp_commit();
            }
            if (kt < 7) cp_wait<1>(); else cp_wait<0>();

            int s = kt % 3;
            int cl = (kt + off) & 7;
            uint32_t stA = wbase + s * AW_STAGE;
            uint32_t bl01[4], bl23[4];
            ldsm_x4(bl01, blo0 + (uint32_t)cl * 256);
            ldsm_x4(bl23, blo1 + (uint32_t)cl * 256);
#pragma unroll
            for (int mf = 0; mf < 4; mf++) {
                uint32_t ah[4], al[4];
                ldsm_x4(ah, stA + aoffs[mf]);
                ldsm_x4(al, stA + aoffs[mf] + AW_PLANE);
#pragma unroll
                for (int nf = 0; nf < 4; nf++) {
                    const uint32_t* bhp = &Bh[kt][nf * 2];
                    const uint32_t* blp = (nf < 2) ? &bl01[nf * 2] : &bl23[(nf - 2) * 2];
                    mma_bf16(acc[mf][nf], ah, bhp);
                    mma_bf16(acc[mf][nf], ah, blp);
                    mma_bf16(acc[mf][nf], al, bhp);
                }
            }
        }

        // ---- store per-warp partials into ring area ----
        __syncthreads();    // all warps drained their rings
#pragma unroll
        for (int mf = 0; mf < 4; mf++)
#pragma unroll
            for (int nf = 0; nf < 4; nf++)
#pragma unroll
                for (int half = 0; half < 2; half++) {
                    int m = mf * 16 + g + half * 8;
                    int n = nf * 8 + tg * 2;
                    float2 v;
                    v.x = acc[mf][nf][half * 2];
                    v.y = acc[mf][nf][half * 2 + 1];
                    *(float2*)&part[(warp * 64 + m) * PART_STR + n] = v;
                }
        __syncthreads();

        // ---- reduce 8 partials + P, tanh, split-store ----
        float s0[4], s1[4];
        {
            int base0 = em * PART_STR + enq * 8;
            float4 v0 = *(const float4*)&part[base0];
            float4 v1 = *(const float4*)&part[base0 + 4];
            s0[0] = v0.x; s0[1] = v0.y; s0[2] = v0.z; s0[3] = v0.w;
            s1[0] = v1.x; s1[1] = v1.y; s1[2] = v1.z; s1[3] = v1.w;
#pragma unroll
            for (int w = 1; w < 8; w++) {
                int base = (w * 64 + em) * PART_STR + enq * 8;
                float4 u0 = *(const float4*)&part[base];
                float4 u1 = *(const float4*)&part[base + 4];
                s0[0] += u0.x; s0[1] += u0.y; s0[2] += u0.z; s0[3] += u0.w;
                s1[0] += u1.x; s1[1] += u1.y; s1[2] += u1.z; s1[3] += u1.w;
            }
        }
        s0[0] += pre[0][0].x; s0[1] += pre[0][0].y;
        s0[2] += pre[0][1].x; s0[3] += pre[0][1].y;
        s1[0] += pre[1][0].x; s1[1] += pre[1][0].y;
        s1[2] += pre[1][1].x; s1[3] += pre[1][1].y;

        {
            float hv[8];
#pragma unroll
            for (int e = 0; e < 4; e++) { hv[e] = tanhf(s0[e]); hv[4 + e] = tanhf(s1[e]); }
            uint32_t hp[4], lp[4];
#pragma unroll
            for (int e = 0; e < 4; e++) {
                __nv_bfloat16 a = __float2bfloat16(hv[2 * e]);
                __nv_bfloat16 b = __float2bfloat16(hv[2 * e + 1]);
                hp[e] = pack_bf162(a, b);
                lp[e] = pack_bf162(
                    __float2bfloat16(hv[2 * e]     - __bfloat162float(a)),
                    __float2bfloat16(hv[2 * e + 1] - __bfloat162float(b)));
            }
            uint4 hv4, lv4;
            hv4.x = hp[0]; hv4.y = hp[1]; hv4.z = hp[2]; hv4.w = hp[3];
            lv4.x = lp[0]; lv4.y = lp[1]; lv4.z = lp[2]; lv4.w = lp[3];
            size_t obase = (size_t)(t + 1) * BH + (size_t)(m0 + em) * H_ + n0 + enq * 8;
            *(uint4*)(g_Hhi + obase) = hv4;
            *(uint4*)(g_Hlo + obase) = lv4;
        }

        // ---- group barrier: publish, arrive (release), prefetch P, spin ----
        __syncthreads();
        if (tid == 0) red_release_add(bar);
        {
            int tn = (t + 1 < T_) ? (t + 1) : t;
            const float* Pp = g_P + (size_t)tn * BH + (size_t)(m0 + em) * H_ + n0 + enq * 8;
            pre[0][0] = *(const float2*)(Pp);
            pre[0][1] = *(const float2*)(Pp + 2);
            pre[1][0] = *(const float2*)(Pp + 4);
            pre[1][1] = *(const float2*)(Pp + 6);
        }
        if (tid == 0) {
            unsigned target = 32u * (unsigned)(t + 1);
            while (ld_acquire(bar) < target) __nanosleep(32);
        }
        __syncthreads();
    }
}

// ---------------- split / misc kernels -------------------------------------
__device__ __forceinline__ void split1(float v, __nv_bfloat16* hi, __nv_bfloat16* lo) {
    __nv_bfloat16 h = __float2bfloat16(v);
    *hi = h;
    *lo = __float2bfloat16(v - __bfloat162float(h));
}

__global__ void split_all_kernel(const float* __restrict__ wxh,
                                 const float* __restrict__ whh,
                                 const float* __restrict__ why,
                                 const float* __restrict__ h0)
{
    if (blockIdx.x == 0 && threadIdx.x < 4) g_bar[threadIdx.x * 32] = 0;
    int i = blockIdx.x * 256 + threadIdx.x;
    const int N1 = D_ * H_;
    const int N2 = N1 + H_ * H_;
    const int N3 = N2 + H_ * O_;
    const int N4 = N3 + BH;
    if (i < N1)      split1(wxh[i],      &g_Wxh_hi[i],      &g_Wxh_lo[i]);
    else if (i < N2) split1(whh[i - N1], &g_Whh_hi[i - N1], &g_Whh_lo[i - N1]);
    else if (i < N3) split1(why[i - N2], &g_Why_hi[i - N2], &g_Why_lo[i - N2]);
    else if (i < N4) split1(h0[i - N3],  &g_Hhi[i - N3],    &g_Hlo[i - N3]);
}

__global__ void split_X_kernel(const float* __restrict__ x)
{
    size_t i = (size_t)blockIdx.x * 256 + threadIdx.x;
    if (i < BTD) split1(x[i], &g_Xhi[i], &g_Xlo[i]);
}

__global__ void final_h_kernel(float* __restrict__ out)
{
    int i = blockIdx.x * 256 + threadIdx.x;
    if (i < BH) {
        size_t o = (size_t)T_ * BH + i;
        out[BTO + i] = __bfloat162float(g_Hhi[o]) + __bfloat162float(g_Hlo[o]);
    }
}

// ---------------- launch ---------------------------------------------------
extern "C" void kernel_launch(void* const* d_in, const int* in_sizes, int n_in,
                              void* d_out, int out_size)
{
    (void)in_sizes; (void)n_in; (void)out_size;
    const float* x    = (const float*)d_in[0];
    const float* h0   = (const float*)d_in[1];
    const float* w_xh = (const float*)d_in[2];
    const float* w_hh = (const float*)d_in[3];
    const float* w_hy = (const float*)d_in[4];
    float* out = (float*)d_out;

    cudaFuncSetAttribute(rnn_persistent_kernel,
                         cudaFuncAttributeMaxDynamicSharedMemorySize, SMEM_RNN);
    cudaFuncSetAttribute(gemm_P_kernel,
                         cudaFuncAttributeMaxDynamicSharedMemorySize, SMEM_G);
    cudaFuncSetAttribute(gemm_Y_kernel,
                         cudaFuncAttributeMaxDynamicSharedMemorySize, SMEM_G);

    // 0: weights + h0 splits (+barrier reset)
    {
        int total = D_ * H_ + H_ * H_ + H_ * O_ + BH;
        split_all_kernel<<<(total + 255) / 256, 256>>>(w_xh, w_hh, w_hy, h0);
    }
    // 1: X split
    split_X_kernel<<<(int)((BTD + 255) / 256), 256>>>(x);
    // 2: P = X @ W_xh  (layout [t][b][h])
    gemm_P_kernel<<<dim3(H_ / 128, (B_ * T_) / 128), 256, SMEM_G>>>();
    // 3: persistent recurrence (register-W, per-warp private A rings)
    rnn_persistent_kernel<<<128, 256, SMEM_RNN>>>();
    // 4: Y = H_all @ W_hy
    gemm_Y_kernel<<<dim3(O_ / 128, (B_ * T_) / 128), 256, SMEM_G>>>(out);
    // 5: final h
    final_h_kernel<<<(BH + 255) / 256, 256>>>(out);
}

// round 15
// speedup vs baseline: 1.3667x; 1.3667x over previous
#include <cuda_runtime.h>
#include <cuda_bf16.h>
#include <cstdint>
#include <cstddef>

// Problem dims
#define B_ 256
#define T_ 512
#define D_ 512
#define H_ 1024
#define O_ 512

constexpr int    BH  = B_ * H_;                      // 262144
constexpr size_t BTH = (size_t)B_ * T_ * H_;         // 134217728
constexpr size_t BTO = (size_t)B_ * T_ * O_;         // 67108864

// ---------------- scratch (static __device__ arrays; no runtime alloc) ----
__device__ __align__(16) float         g_P[BTH];                     // [t][b][h]
__device__ __align__(16) __nv_bfloat16 g_Hhi[(size_t)(T_ + 1) * BH]; // split h, hi
__device__ __align__(16) __nv_bfloat16 g_Hlo[(size_t)(T_ + 1) * BH]; // split h, lo
__device__ __align__(16) __nv_bfloat16 g_Wxh_hi[D_ * H_], g_Wxh_lo[D_ * H_];
__device__ __align__(16) __nv_bfloat16 g_Whh_hi[H_ * H_], g_Whh_lo[H_ * H_];
__device__ __align__(16) __nv_bfloat16 g_Why_hi[H_ * O_], g_Why_lo[H_ * O_];
__device__ unsigned      g_bar[4 * 32];              // group barriers (128B apart)

// ---------------- PTX helpers ---------------------------------------------
__device__ __forceinline__ void mma_bf16(float* c, const uint32_t* a, const uint32_t* b) {
    asm volatile(
        "mma.sync.aligned.m16n8k16.row.col.f32.bf16.bf16.f32 "
        "{%0,%1,%2,%3}, {%4,%5,%6,%7}, {%8,%9}, {%0,%1,%2,%3};\n"
        : "+f"(c[0]), "+f"(c[1]), "+f"(c[2]), "+f"(c[3])
        : "r"(a[0]), "r"(a[1]), "r"(a[2]), "r"(a[3]), "r"(b[0]), "r"(b[1]));
}
__device__ __forceinline__ void ldsm_x4(uint32_t* r, uint32_t saddr) {
    asm volatile("ldmatrix.sync.aligned.m8n8.x4.shared.b16 {%0,%1,%2,%3}, [%4];"
                 : "=r"(r[0]), "=r"(r[1]), "=r"(r[2]), "=r"(r[3]) : "r"(saddr));
}
__device__ __forceinline__ void ldsm_x4_t(uint32_t* r, uint32_t saddr) {
    asm volatile("ldmatrix.sync.aligned.m8n8.x4.trans.shared.b16 {%0,%1,%2,%3}, [%4];"
                 : "=r"(r[0]), "=r"(r[1]), "=r"(r[2]), "=r"(r[3]) : "r"(saddr));
}
__device__ __forceinline__ void cpasync16(uint32_t smem_addr, const void* gmem) {
    asm volatile("cp.async.ca.shared.global [%0], [%1], 16;\n"
                 :: "r"(smem_addr), "l"(gmem));
}
__device__ __forceinline__ void cp_commit() {
    asm volatile("cp.async.commit_group;\n" ::: "memory");
}
template <int N>
__device__ __forceinline__ void cp_wait() {
    asm volatile("cp.async.wait_group %0;\n" :: "n"(N) : "memory");
}
__device__ __forceinline__ void red_release_add(unsigned* p) {
    asm volatile("red.release.gpu.global.add.u32 [%0], 1;" :: "l"(p) : "memory");
}
__device__ __forceinline__ unsigned ld_acquire(const unsigned* p) {
    unsigned v;
    asm volatile("ld.acquire.gpu.u32 %0, [%1];" : "=r"(v) : "l"(p));
    return v;
}
__device__ __forceinline__ uint32_t pack_bf162(__nv_bfloat16 a, __nv_bfloat16 b) {
    __nv_bfloat162 t; t.x = a; t.y = b;
    uint32_t r;
    __builtin_memcpy(&r, &t, 4);
    return r;
}

// =================== big GEMM (P and Y) geometry ===========================
constexpr int SGA   = 40;
constexpr int SBN   = 136;
constexpr int GA_PL = 128 * SGA * 2;           // 10240 B per A plane
constexpr int GB_PL = 32 * SBN * 2;            // 8704 B per B plane
constexpr int G_STAGE = 2 * GA_PL + 2 * GB_PL; // 37888
constexpr int SMEM_G  = 2 * G_STAGE;           // 75776

__device__ __forceinline__ void g_loadB(uint32_t st, const __nv_bfloat16* Bhi,
                                        const __nv_bfloat16* Blo, int ldb,
                                        int n0, int k0, int tid)
{
#pragma unroll
    for (int j = 0; j < 4; j++) {
        int idx = j * 256 + tid;
        int plane = idx >> 9, rem = idx & 511;
        int k = rem >> 4, n16 = rem & 15;
        const __nv_bfloat16* src = (plane ? Blo : Bhi) + (size_t)(k0 + k) * ldb + n0 + n16 * 8;
        cpasync16(st + 2 * GA_PL + plane * GB_PL + (uint32_t)(k * SBN + n16 * 8) * 2, src);
    }
}

__device__ __forceinline__ void g_compute(uint32_t stA, uint32_t aoff, uint32_t boff,
                                          float acc[2][8][4])
{
    uint32_t stB = stA + 2 * GA_PL;
#pragma unroll
    for (int ks = 0; ks < 32; ks += 16) {
        uint32_t ah0[4], ah1[4], al0[4], al1[4];
        ldsm_x4(ah0, stA + aoff + ks * 2);
        ldsm_x4(ah1, stA + aoff + ks * 2 + 16 * SGA * 2);
        ldsm_x4(al0, stA + GA_PL + aoff + ks * 2);
        ldsm_x4(al1, stA + GA_PL + aoff + ks * 2 + 16 * SGA * 2);
#pragma unroll
        for (int hn = 0; hn < 2; hn++) {
            uint32_t bb0 = stB + boff + (uint32_t)(ks * SBN + hn * 32) * 2;
            uint32_t bh0[4], bh1[4], bl0[4], bl1[4];
            ldsm_x4_t(bh0, bb0);
            ldsm_x4_t(bh1, bb0 + 32);
            ldsm_x4_t(bl0, bb0 + GB_PL);
            ldsm_x4_t(bl1, bb0 + GB_PL + 32);
#pragma unroll
            for (int mf = 0; mf < 2; mf++) {
                const uint32_t* Ah = mf ? ah1 : ah0;
                const uint32_t* Al = mf ? al1 : al0;
                float* a0 = acc[mf][hn * 4 + 0];
                float* a1 = acc[mf][hn * 4 + 1];
                float* a2 = acc[mf][hn * 4 + 2];
                float* a3 = acc[mf][hn * 4 + 3];
                mma_bf16(a0, Ah, bh0 + 0);  mma_bf16(a1, Ah, bh0 + 2);
                mma_bf16(a2, Ah, bh1 + 0);  mma_bf16(a3, Ah, bh1 + 2);
                mma_bf16(a0, Ah, bl0 + 0);  mma_bf16(a1, Ah, bl0 + 2);
                mma_bf16(a2, Ah, bl1 + 0);  mma_bf16(a3, Ah, bl1 + 2);
                mma_bf16(a0, Al, bh0 + 0);  mma_bf16(a1, Al, bh0 + 2);
                mma_bf16(a2, Al, bh1 + 0);  mma_bf16(a3, Al, bh1 + 2);
            }
        }
    }
}

// ---------------- kernel: P = split(X) @ split(W_xh), out [t][b][h] -------
// X is read as fp32 directly (LDG float4, prefetched one k-tile ahead),
// split to bf16 hi/lo in registers, stored to smem — no pre-split pass.
__global__ __launch_bounds__(256, 2) void gemm_P_kernel(const float* __restrict__ X)
{
    extern __shared__ __align__(16) char gsm[];
    uint32_t sb = (uint32_t)__cvta_generic_to_shared(gsm);
    int tid = threadIdx.x, lane = tid & 31, warp = tid >> 5;
    int g = lane >> 2, tg = lane & 3;
    int wm = (warp >> 1) * 32, wn = (warp & 1) * 64;
    int n0 = blockIdx.x * 128;
    int m0 = blockIdx.y * 128;
    const int NK = D_ / 32;  // 16

    // X tile mapping: 128 rows x 32 cols = 1024 float4 units, 4/thread
    const int xrow = (tid * 4 + 0) >> 5 * 0;  // placeholder (computed per j)

    const uint32_t aoff =
        (uint32_t)((wm + ((lane >> 3) & 1) * 8 + (lane & 7)) * SGA + (lane >> 4) * 8) * 2;
    const uint32_t boff =
        (uint32_t)((((lane >> 3) & 1) * 8 + (lane & 7)) * SBN + wn + (lane >> 4) * 8) * 2;

    float acc[2][8][4];
#pragma unroll
    for (int a = 0; a < 2; a++)
#pragma unroll
        for (int b = 0; b < 8; b++)
#pragma unroll
            for (int c = 0; c < 4; c++) acc[a][b][c] = 0.f;

    // helper lambdas via macros: unit u -> row = u>>3, c4 = u&7
#define XP_LDG(dst, kt)                                                        \
    {                                                                          \
        _Pragma("unroll")                                                      \
        for (int j = 0; j < 4; j++) {                                          \
            int u = j * 256 + tid;                                             \
            int row = u >> 3, c4 = u & 7;                                      \
            dst[j] = *(const float4*)(X + (size_t)(m0 + row) * D_ +            \
                                      (kt) * 32 + c4 * 4);                     \
        }                                                                      \
    }
#define XP_STS(src, st)                                                        \
    {                                                                          \
        _Pragma("unroll")                                                      \
        for (int j = 0; j < 4; j++) {                                          \
            int u = j * 256 + tid;                                             \
            int row = u >> 3, c4 = u & 7;                                      \
            float v0 = src[j].x, v1 = src[j].y, v2 = src[j].z, v3 = src[j].w;  \
            __nv_bfloat16 h0 = __float2bfloat16(v0);                           \
            __nv_bfloat16 h1 = __float2bfloat16(v1);                           \
            __nv_bfloat16 h2 = __float2bfloat16(v2);                           \
            __nv_bfloat16 h3 = __float2bfloat16(v3);                           \
            uint32_t hi01 = pack_bf162(h0, h1);                                \
            uint32_t hi23 = pack_bf162(h2, h3);                                \
            uint32_t lo01 = pack_bf162(                                        \
                __float2bfloat16(v0 - __bfloat162float(h0)),                   \
                __float2bfloat16(v1 - __bfloat162float(h1)));                  \
            uint32_t lo23 = pack_bf162(                                        \
                __float2bfloat16(v2 - __bfloat162float(h2)),                   \
                __float2bfloat16(v3 - __bfloat162float(h3)));                  \
            uint32_t base = (st) + (uint32_t)(row * SGA + c4 * 4) * 2;         \
            *(uint32_t*)(gsm + (base - sb))         = hi01;                    \
            *(uint32_t*)(gsm + (base - sb) + 4)     = hi23;                    \
            *(uint32_t*)(gsm + (base - sb) + GA_PL)     = lo01;                \
            *(uint32_t*)(gsm + (base - sb) + GA_PL + 4) = lo23;                \
        }                                                                      \
    }

    // prologue: X tile 0 -> regs -> smem stage 0; B tile 0 via cp.async
    float4 xv[4];
    XP_LDG(xv, 0);
    XP_STS(xv, sb);
    g_loadB(sb, g_Wxh_hi, g_Wxh_lo, H_, n0, 0, tid);
    cp_commit();

    float4 xn[4];
    for (int kt = 0; kt < NK; kt++) {
        uint32_t cur = sb + (uint32_t)(kt & 1) * G_STAGE;
        if (kt + 1 < NK) {
            XP_LDG(xn, kt + 1);                       // LDG early (hidden)
            uint32_t nst = sb + (uint32_t)((kt + 1) & 1) * G_STAGE;
            g_loadB(nst, g_Wxh_hi, g_Wxh_lo, H_, n0, (kt + 1) * 32, tid);
            cp_commit();
            cp_wait<1>();
        } else {
            cp_wait<0>();
        }
        __syncthreads();
        g_compute(cur, aoff, boff, acc);
        __syncthreads();
        if (kt + 1 < NK) {
            uint32_t nst = sb + (uint32_t)((kt + 1) & 1) * G_STAGE;
            XP_STS(xn, nst);                          // visible after next sync
        }
    }
#undef XP_LDG
#undef XP_STS

    // scatter to g_P [t][b][h]
#pragma unroll
    for (int mf = 0; mf < 2; mf++)
#pragma unroll
        for (int nf = 0; nf < 8; nf++) {
            int c = n0 + wn + nf * 8 + tg * 2;
#pragma unroll
            for (int half = 0; half < 2; half++) {
                int r = m0 + wm + mf * 16 + g + half * 8;
                int tt = r & (T_ - 1);
                int bb = r >> 9;
                float2 v;
                v.x = acc[mf][nf][half * 2];
                v.y = acc[mf][nf][half * 2 + 1];
                *(float2*)(g_P + ((size_t)tt * B_ + bb) * H_ + c) = v;
            }
        }
    (void)xrow;
}

// ---------------- kernel: Y = H_all @ W_hy --------------------------------
__global__ __launch_bounds__(256, 2) void gemm_Y_kernel(float* __restrict__ out)
{
    extern __shared__ __align__(16) char gsm[];
    uint32_t sb = (uint32_t)__cvta_generic_to_shared(gsm);
    int tid = threadIdx.x, lane = tid & 31, warp = tid >> 5;
    int g = lane >> 2, tg = lane & 3;
    int wm = (warp >> 1) * 32, wn = (warp & 1) * 64;
    int n0 = blockIdx.x * 128;
    int m0 = blockIdx.y * 128;
    const int NK = H_ / 32;  // 32

    const uint32_t aoff =
        (uint32_t)((wm + ((lane >> 3) & 1) * 8 + (lane & 7)) * SGA + (lane >> 4) * 8) * 2;
    const uint32_t boff =
        (uint32_t)((((lane >> 3) & 1) * 8 + (lane & 7)) * SBN + wn + (lane >> 4) * 8) * 2;

    float acc[2][8][4];
#pragma unroll
    for (int a = 0; a < 2; a++)
#pragma unroll
        for (int b = 0; b < 8; b++)
#pragma unroll
            for (int c = 0; c < 4; c++) acc[a][b][c] = 0.f;

#pragma unroll
    for (int j = 0; j < 4; j++) {
        int idx = j * 256 + tid;
        int plane = idx >> 9, rem = idx & 511;
        int r = rem >> 2, c4 = rem & 3;
        int m = m0 + r;
        int tt = m & (T_ - 1), bb = m >> 9;
        const __nv_bfloat16* src = (plane ? g_Hlo : g_Hhi) +
            (size_t)(tt + 1) * BH + (size_t)bb * H_ + c4 * 8;
        cpasync16(sb + plane * GA_PL + (uint32_t)(r * SGA + c4 * 8) * 2, src);
    }
    g_loadB(sb, g_Why_hi, g_Why_lo, O_, n0, 0, tid);
    cp_commit();

    for (int kt = 0; kt < NK; kt++) {
        if (kt + 1 < NK) {
            uint32_t st = sb + ((kt + 1) & 1) * G_STAGE;
            int k0 = (kt + 1) * 32;
#pragma unroll
            for (int j = 0; j < 4; j++) {
                int idx = j * 256 + tid;
                int plane = idx >> 9, rem = idx & 511;
                int r = rem >> 2, c4 = rem & 3;
                int m = m0 + r;
                int tt = m & (T_ - 1), bb = m >> 9;
                const __nv_bfloat16* src = (plane ? g_Hlo : g_Hhi) +
                    (size_t)(tt + 1) * BH + (size_t)bb * H_ + k0 + c4 * 8;
                cpasync16(st + plane * GA_PL + (uint32_t)(r * SGA + c4 * 8) * 2, src);
            }
            g_loadB(st, g_Why_hi, g_Why_lo, O_, n0, k0, tid);
            cp_commit();
            cp_wait<1>();
        } else {
            cp_wait<0>();
        }
        __syncthreads();
        g_compute(sb + (kt & 1) * G_STAGE, aoff, boff, acc);
        __syncthreads();
    }

#pragma unroll
    for (int mf = 0; mf < 2; mf++)
#pragma unroll
        for (int nf = 0; nf < 8; nf++) {
            int c = n0 + wn + nf * 8 + tg * 2;
#pragma unroll
            for (int half = 0; half < 2; half++) {
                size_t r = (size_t)m0 + wm + mf * 16 + g + half * 8;
                float2 v;
                v.x = acc[mf][nf][half * 2];
                v.y = acc[mf][nf][half * 2 + 1];
                *(float2*)(out + r * O_ + c) = v;
            }
        }
}

// =================== persistent recurrence kernel (R11, proven) ============
// 128 CTAs = 4 groups (64 batch rows) x 32 n-tiles (32 cols), 256 thr (8 warps).
// k-interleaved warp specialization: warp w owns k16-slice w of every k128
// chunk; its W_hh-hi B-fragments live in REGISTERS (loaded once). W_hh-lo
// stays in smem. Per-warp 64x32 k-partials reduced through smem each step.
constexpr int SW       = 1032;                       // W-lo slab row stride (elems)
constexpr int SM_WLO   = 1024;
constexpr int SM_ABASE = SM_WLO + 32 * SW * 2;       // 67072
constexpr int ST_ROW   = 136;                        // A stage row stride (elems)
constexpr int A_PLANE2 = 64 * ST_ROW * 2;            // 17408 B
constexpr int A_STAGE2 = 2 * A_PLANE2;               // 34816 B
constexpr int SMEM_RNN = SM_ABASE + 3 * A_STAGE2;    // 171520 B
constexpr int PART_STR = 36;                         // partial stride (floats), 16B-mult

__global__ __launch_bounds__(256, 1) void rnn_persistent_kernel()
{
    extern __shared__ __align__(1024) char smem[];
    uint32_t sb = (uint32_t)__cvta_generic_to_shared(smem);

    const int tid  = threadIdx.x;
    const int lane = tid & 31, warp = tid >> 5;      // 8 warps
    const int g = lane >> 2, tg = lane & 3;
    const int grp = (int)(blockIdx.x >> 5);
    const int m0 = grp * 64;
    const int n0 = (int)(blockIdx.x & 31) * 32;
    const int off = (int)(blockIdx.x & 7);           // chunk stagger (8 chunks)
    unsigned* bar = &g_bar[grp * 32];

    // ---- load W-lo slab (resident) + W-hi temp slab (stage area) ----
    __nv_bfloat16* sWlo  = (__nv_bfloat16*)(smem + SM_WLO);
    __nv_bfloat16* sWhiT = (__nv_bfloat16*)(smem + SM_ABASE);
    for (int idx = tid; idx < 32 * 1024; idx += 256) {
        int n = idx & 31, k = idx >> 5;
        sWlo[n * SW + k]  = g_Whh_lo[(size_t)k * H_ + n0 + n];
        sWhiT[n * SW + k] = g_Whh_hi[(size_t)k * H_ + n0 + n];
    }
    __syncthreads();

    // ---- B lane addressing ----
    const int bn  = (lane >> 4) * 8 + (lane & 7);    // n within 16-group
    const int kb  = ((lane >> 3) & 1) * 8;           // k8 offset
    // W-hi fragments -> registers; Bh[i] holds the i-th PROCESSED chunk
    uint32_t Bh[8][8];
#pragma unroll
    for (int i = 0; i < 8; i++) {
        int cl = (i + off) & 7;
        int k16 = cl * 8 + warp;                     // global k16 index
        uint32_t a0 = sb + SM_ABASE + (uint32_t)(bn * SW + k16 * 16 + kb) * 2;
        uint32_t a1 = a0 + (uint32_t)(16 * SW) * 2;
        ldsm_x4(&Bh[i][0], a0);
        ldsm_x4(&Bh[i][4], a1);
    }
    __syncthreads();    // W-hi temp slab now free (stage area)

    // ---- A / B-lo lane addressing ----
    const int a_row = (lane & 7) + ((lane >> 3) & 1) * 8;    // 0..15
    const uint32_t a_k = (uint32_t)((lane >> 4) * 8);
    uint32_t aoffs[4];
#pragma unroll
    for (int mf = 0; mf < 4; mf++)
        aoffs[mf] = (uint32_t)((mf * 16 + a_row) * ST_ROW + warp * 16 + a_k) * 2;
    const uint32_t blo0 = sb + SM_WLO + (uint32_t)(bn * SW + warp * 16 + kb) * 2;
    const uint32_t blo1 = blo0 + (uint32_t)(16 * SW) * 2;

    // ---- epilogue mapping ----
    const int em  = tid >> 2;                        // 0..63 output row
    const int enq = tid & 3;                         // n-quad (8 cols)

    float* part = (float*)(smem + SM_ABASE);         // overlays stage area

    for (int t = 0; t < T_; t++) {
        const __nv_bfloat16* bHi = g_Hhi + (size_t)t * BH + (size_t)m0 * H_;
        const __nv_bfloat16* bLo = g_Hlo + (size_t)t * BH + (size_t)m0 * H_;

        float acc[4][4][4];
#pragma unroll
        for (int a = 0; a < 4; a++)
#pragma unroll
            for (int b = 0; b < 4; b++)
#pragma unroll
                for (int e = 0; e < 4; e++) acc[a][b][e] = 0.f;

        // ---- prologue: chunks (off), (off+1) into stages 0, 1 ----
        // full chunk = 64 rows x 128 k (256 B/row) x 2 planes = 2048 x 16B
#pragma unroll
        for (int pk = 0; pk < 2; pk++) {
            int cl = (pk + off) & 7;
#pragma unroll
            for (int j = 0; j < 8; j++) {
                int idx = j * 256 + tid;
                int plane = idx >> 10, rem = idx & 1023;
                int row = rem >> 4, c16 = rem & 15;
                uint32_t dst = sb + SM_ABASE + pk * A_STAGE2 + plane * A_PLANE2 +
                               (uint32_t)(row * ST_ROW + c16 * 8) * 2;
                const __nv_bfloat16* src =
                    (plane ? bLo : bHi) + (size_t)row * H_ + cl * 128 + c16 * 8;
                cpasync16(dst, src);
            }
            cp_commit();
        }

        for (int kt = 0; kt < 8; kt++) {
            if (kt < 7) cp_wait<1>(); else cp_wait<0>();
            __syncthreads();

            if (kt + 2 < 8) {
                int s2 = (kt + 2) % 3;
                int cl2 = (kt + 2 + off) & 7;
#pragma unroll
                for (int j = 0; j < 8; j++) {
                    int idx = j * 256 + tid;
                    int plane = idx >> 10, rem = idx & 1023;
                    int row = rem >> 4, c16 = rem & 15;
                    uint32_t dst = sb + SM_ABASE + s2 * A_STAGE2 + plane * A_PLANE2 +
                                   (uint32_t)(row * ST_ROW + c16 * 8) * 2;
                    const __nv_bfloat16* src =
                        (plane ? bLo : bHi) + (size_t)row * H_ + cl2 * 128 + c16 * 8;
                    cpasync16(dst, src);
                }
                cp_commit();
            }

            int s = kt % 3;
            int cl = (kt + off) & 7;
            uint32_t stA = sb + SM_ABASE + s * A_STAGE2;
            uint32_t bl01[4], bl23[4];
            ldsm_x4(bl01, blo0 + (uint32_t)cl * 256);
            ldsm_x4(bl23, blo1 + (uint32_t)cl * 256);
#pragma unroll
            for (int mf = 0; mf < 4; mf++) {
                uint32_t ah[4], al[4];
                ldsm_x4(ah, stA + aoffs[mf]);
                ldsm_x4(al, stA + aoffs[mf] + A_PLANE2);
#pragma unroll
                for (int nf = 0; nf < 4; nf++) {
                    const uint32_t* bhp = &Bh[kt][nf * 2];
                    const uint32_t* blp = (nf < 2) ? &bl01[nf * 2] : &bl23[(nf - 2) * 2];
                    mma_bf16(acc[mf][nf], ah, bhp);
                    mma_bf16(acc[mf][nf], ah, blp);
                    mma_bf16(acc[mf][nf], al, bhp);
                }
            }
        }

        // ---- prefetch P for this thread's outputs (consumed after reduce) --
        const float* Pp = g_P + (size_t)t * BH + (size_t)(m0 + em) * H_ + n0 + enq * 8;
        float4 p0 = *(const float4*)(Pp);
        float4 p1 = *(const float4*)(Pp + 4);

        // ---- store per-warp partials into stage area (now free) ----
        __syncthreads();    // all warps done reading stages
#pragma unroll
        for (int mf = 0; mf < 4; mf++)
#pragma unroll
            for (int nf = 0; nf < 4; nf++)
#pragma unroll
                for (int half = 0; half < 2; half++) {
                    int m = mf * 16 + g + half * 8;
                    int n = nf * 8 + tg * 2;
                    float2 v;
                    v.x = acc[mf][nf][half * 2];
                    v.y = acc[mf][nf][half * 2 + 1];
                    *(float2*)&part[(warp * 64 + m) * PART_STR + n] = v;
                }
        __syncthreads();

        // ---- reduce 8 partials + P, tanh, split-store ----
        float s0[4], s1[4];
        {
            int base0 = em * PART_STR + enq * 8;
            float4 v0 = *(const float4*)&part[base0];
            float4 v1 = *(const float4*)&part[base0 + 4];
            s0[0] = v0.x; s0[1] = v0.y; s0[2] = v0.z; s0[3] = v0.w;
            s1[0] = v1.x; s1[1] = v1.y; s1[2] = v1.z; s1[3] = v1.w;
#pragma unroll
            for (int w = 1; w < 8; w++) {
                int base = (w * 64 + em) * PART_STR + enq * 8;
                float4 u0 = *(const float4*)&part[base];
                float4 u1 = *(const float4*)&part[base + 4];
                s0[0] += u0.x; s0[1] += u0.y; s0[2] += u0.z; s0[3] += u0.w;
                s1[0] += u1.x; s1[1] += u1.y; s1[2] += u1.z; s1[3] += u1.w;
            }
        }
        s0[0] += p0.x; s0[1] += p0.y; s0[2] += p0.z; s0[3] += p0.w;
        s1[0] += p1.x; s1[1] += p1.y; s1[2] += p1.z; s1[3] += p1.w;

        {
            float hv[8];
#pragma unroll
            for (int e = 0; e < 4; e++) { hv[e] = tanhf(s0[e]); hv[4 + e] = tanhf(s1[e]); }
            uint32_t hp[4], lp[4];
#pragma unroll
            for (int e = 0; e < 4; e++) {
                __nv_bfloat16 a = __float2bfloat16(hv[2 * e]);
                __nv_bfloat16 b = __float2bfloat16(hv[2 * e + 1]);
                hp[e] = pack_bf162(a, b);
                lp[e] = pack_bf162(
                    __float2bfloat16(hv[2 * e]     - __bfloat162float(a)),
                    __float2bfloat16(hv[2 * e + 1] - __bfloat162float(b)));
            }
            uint4 hv4, lv4;
            hv4.x = hp[0]; hv4.y = hp[1]; hv4.z = hp[2]; hv4.w = hp[3];
            lv4.x = lp[0]; lv4.y = lp[1]; lv4.z = lp[2]; lv4.w = lp[3];
            size_t obase = (size_t)(t + 1) * BH + (size_t)(m0 + em) * H_ + n0 + enq * 8;
            *(uint4*)(g_Hhi + obase) = hv4;
            *(uint4*)(g_Hlo + obase) = lv4;
        }

        // ---- group barrier ----
        __syncthreads();
        if (tid == 0) red_release_add(bar);
        if (tid == 0) {
            unsigned target = 32u * (unsigned)(t + 1);
            while (ld_acquire(bar) < target) __nanosleep(32);
        }
        __syncthreads();
    }
}

// ---------------- split / misc kernels -------------------------------------
__device__ __forceinline__ void split1(float v, __nv_bfloat16* hi, __nv_bfloat16* lo) {
    __nv_bfloat16 h = __float2bfloat16(v);
    *hi = h;
    *lo = __float2bfloat16(v - __bfloat162float(h));
}

__global__ void split_all_kernel(const float* __restrict__ wxh,
                                 const float* __restrict__ whh,
                                 const float* __restrict__ why,
                                 const float* __restrict__ h0)
{
    if (blockIdx.x == 0 && threadIdx.x < 4) g_bar[threadIdx.x * 32] = 0;
    int i = blockIdx.x * 256 + threadIdx.x;
    const int N1 = D_ * H_;
    const int N2 = N1 + H_ * H_;
    const int N3 = N2 + H_ * O_;
    const int N4 = N3 + BH;
    if (i < N1)      split1(wxh[i],      &g_Wxh_hi[i],      &g_Wxh_lo[i]);
    else if (i < N2) split1(whh[i - N1], &g_Whh_hi[i - N1], &g_Whh_lo[i - N1]);
    else if (i < N3) split1(why[i - N2], &g_Why_hi[i - N2], &g_Why_lo[i - N2]);
    else if (i < N4) split1(h0[i - N3],  &g_Hhi[i - N3],    &g_Hlo[i - N3]);
}

__global__ void final_h_kernel(float* __restrict__ out)
{
    int i = blockIdx.x * 256 + threadIdx.x;
    if (i < BH) {
        size_t o = (size_t)T_ * BH + i;
        out[BTO + i] = __bfloat162float(g_Hhi[o]) + __bfloat162float(g_Hlo[o]);
    }
}

// ---------------- launch ---------------------------------------------------
extern "C" void kernel_launch(void* const* d_in, const int* in_sizes, int n_in,
                              void* d_out, int out_size)
{
    (void)in_sizes; (void)n_in; (void)out_size;
    const float* x    = (const float*)d_in[0];
    const float* h0   = (const float*)d_in[1];
    const float* w_xh = (const float*)d_in[2];
    const float* w_hh = (const float*)d_in[3];
    const float* w_hy = (const float*)d_in[4];
    float* out = (float*)d_out;

    cudaFuncSetAttribute(rnn_persistent_kernel,
                         cudaFuncAttributeMaxDynamicSharedMemorySize, SMEM_RNN);
    cudaFuncSetAttribute(gemm_P_kernel,
                         cudaFuncAttributeMaxDynamicSharedMemorySize, SMEM_G);
    cudaFuncSetAttribute(gemm_Y_kernel,
                         cudaFuncAttributeMaxDynamicSharedMemorySize, SMEM_G);

    // 0: weights + h0 splits (+barrier reset)
    {
        int total = D_ * H_ + H_ * H_ + H_ * O_ + BH;
        split_all_kernel<<<(total + 255) / 256, 256>>>(w_xh, w_hh, w_hy, h0);
    }
    // 1: P = X @ W_xh  (X split fused in; layout [t][b][h])
    gemm_P_kernel<<<dim3(H_ / 128, (B_ * T_) / 128), 256, SMEM_G>>>(x);
    // 2: persistent recurrence (register-W, k-interleaved; proven R11 core)
    rnn_persistent_kernel<<<128, 256, SMEM_RNN>>>();
    // 3: Y = H_all @ W_hy
    gemm_Y_kernel<<<dim3(O_ / 128, (B_ * T_) / 128), 256, SMEM_G>>>(out);
    // 4: final h
    final_h_kernel<<<(BH + 255) / 256, 256>>>(out);
}